// round 1
// baseline (speedup 1.0000x reference)
#include <cuda_runtime.h>

#define DM   768
#define NH   12
#define DH   64
#define BB   2
#define TT   4096
#define BH   (BB*NH)

// Scratch (no cudaMalloc allowed): Q/K/V in [B,H,T,Dh], att in [B,T,H,Dh]
__device__ float g_Q[(size_t)BH*TT*DH];
__device__ float g_K[(size_t)BH*TT*DH];
__device__ float g_V[(size_t)BH*TT*DH];
__device__ float g_att[(size_t)BB*TT*DM];

// ---------------------------------------------------------------------------
// GEMM1: qkv = x @ w_qkv^T + b_qkv, scattered into g_Q/g_K/g_V.
// C[m,n] = sum_k x[m,k]*w[n,k].  Tiles 64x64, K-tile 16, 256 thr, 4x4/thread.
// n0 is 64-aligned -> (which, head) constant per block, d = local col.
// Q values pre-scaled by 1/sqrt(64) = 0.125.
// ---------------------------------------------------------------------------
__global__ __launch_bounds__(256) void qkv_kernel(const float* __restrict__ x,
                                                  const float* __restrict__ w,
                                                  const float* __restrict__ bias) {
    __shared__ float As[16][64];   // [k][m]
    __shared__ float Ws[16][64];   // [k][n]
    const int tid = threadIdx.x;
    const int tx = tid & 15, ty = tid >> 4;
    const int n0 = blockIdx.x * 64, m0 = blockIdx.y * 64;
    const int lr = tid >> 2, lk = (tid & 3) * 4;

    const float* aptr = x + (size_t)(m0 + lr) * DM + lk;
    const float* wptr = w + (size_t)(n0 + lr) * DM + lk;

    float acc[4][4] = {};
    for (int k0 = 0; k0 < DM; k0 += 16) {
        float4 a4 = *(const float4*)(aptr + k0);
        float4 w4 = *(const float4*)(wptr + k0);
        As[lk + 0][lr] = a4.x; As[lk + 1][lr] = a4.y;
        As[lk + 2][lr] = a4.z; As[lk + 3][lr] = a4.w;
        Ws[lk + 0][lr] = w4.x; Ws[lk + 1][lr] = w4.y;
        Ws[lk + 2][lr] = w4.z; Ws[lk + 3][lr] = w4.w;
        __syncthreads();
#pragma unroll
        for (int k = 0; k < 16; k++) {
            float a[4], b[4];
            *(float4*)a = *(float4*)&As[k][4 * ty];
            *(float4*)b = *(float4*)&Ws[k][4 * tx];
#pragma unroll
            for (int i = 0; i < 4; i++)
#pragma unroll
                for (int j = 0; j < 4; j++)
                    acc[i][j] += a[i] * b[j];
        }
        __syncthreads();
    }

    const int which = n0 / DM;              // 0=Q 1=K 2=V
    const int head  = (n0 % DM) >> 6;
    float* dst = (which == 0) ? g_Q : ((which == 1) ? g_K : g_V);
    const float scale = (which == 0) ? 0.125f : 1.0f;

    float bia[4];
#pragma unroll
    for (int j = 0; j < 4; j++) bia[j] = bias[n0 + 4 * tx + j];

#pragma unroll
    for (int i = 0; i < 4; i++) {
        int m = m0 + 4 * ty + i;
        int bb = m >> 12, t = m & 4095;
        size_t base = (((size_t)(bb * NH + head)) * TT + t) * DH + 4 * tx;
        float4 o;
        o.x = (acc[i][0] + bia[0]) * scale;
        o.y = (acc[i][1] + bia[1]) * scale;
        o.z = (acc[i][2] + bia[2]) * scale;
        o.w = (acc[i][3] + bia[3]) * scale;
        *(float4*)&dst[base] = o;
    }
}

// ---------------------------------------------------------------------------
// Flash attention: block = (q-tile 64, one (b,h)). 256 threads, 4x4 outputs.
// Qt/Kt stored d-major in smem (conflict-free float4 in the dot loop).
// Softmax stats (m,l) live in registers, reduced across 16 tx lanes by shfl.
// P staged transposed with stride 68 (16B-aligned rows, ~conflict-free reads).
// ---------------------------------------------------------------------------
__global__ __launch_bounds__(256) void attn_kernel(const int* __restrict__ mask,
                                                   float* __restrict__ att) {
    extern __shared__ float sm[];
    float* Qt = sm;                 // Qt[d*64 + r]
    float* Kt = sm + 64 * 64;       // Kt[d*64 + c]
    float* Vs = sm + 2 * 64 * 64;   // Vs[k*64 + c]
    float* Pt = sm + 3 * 64 * 64;   // Pt[c*68 + r]

    const int tid = threadIdx.x;
    const int tx = tid & 15, ty = tid >> 4;
    const int bh = blockIdx.y;
    const int b = bh / NH, head = bh % NH;
    const int q0 = blockIdx.x * 64;

    const float* Qp = g_Q + (size_t)bh * TT * DH;
    const float* Kp = g_K + (size_t)bh * TT * DH;
    const float* Vp = g_V + (size_t)bh * TT * DH;
    const int* mrow_g = mask + (size_t)b * TT;

    // load Q tile transposed
    {
        int r = tid >> 2, d0 = (tid & 3) * 16;
        const float* src = Qp + (size_t)(q0 + r) * DH + d0;
#pragma unroll
        for (int u = 0; u < 4; u++) {
            float4 v = *(const float4*)(src + 4 * u);
            Qt[(d0 + 4 * u + 0) * 64 + r] = v.x;
            Qt[(d0 + 4 * u + 1) * 64 + r] = v.y;
            Qt[(d0 + 4 * u + 2) * 64 + r] = v.z;
            Qt[(d0 + 4 * u + 3) * 64 + r] = v.w;
        }
    }

    float O[4][4] = {};
    float mr[4], lr_[4];
#pragma unroll
    for (int i = 0; i < 4; i++) { mr[i] = -1e30f; lr_[i] = 0.f; }

    for (int jt = 0; jt < TT / 64; jt++) {
        __syncthreads();           // prev PV done (and Qt visible on iter 0)
        // load K (transposed) and V (natural)
        {
            int r = tid >> 2, d0 = (tid & 3) * 16;
            const float* ks = Kp + (size_t)(jt * 64 + r) * DH + d0;
            const float* vs = Vp + (size_t)(jt * 64 + r) * DH + d0;
#pragma unroll
            for (int u = 0; u < 4; u++) {
                float4 kv = *(const float4*)(ks + 4 * u);
                Kt[(d0 + 4 * u + 0) * 64 + r] = kv.x;
                Kt[(d0 + 4 * u + 1) * 64 + r] = kv.y;
                Kt[(d0 + 4 * u + 2) * 64 + r] = kv.z;
                Kt[(d0 + 4 * u + 3) * 64 + r] = kv.w;
                *(float4*)&Vs[r * 64 + d0 + 4 * u] = *(const float4*)(vs + 4 * u);
            }
        }
        __syncthreads();

        // S = Q @ K^T  (Q pre-scaled by 1/sqrt(DH))
        float s[4][4] = {};
#pragma unroll 8
        for (int d = 0; d < 64; d++) {
            float q[4], k[4];
            *(float4*)q = *(float4*)&Qt[d * 64 + 4 * ty];
            *(float4*)k = *(float4*)&Kt[d * 64 + 4 * tx];
#pragma unroll
            for (int i = 0; i < 4; i++)
#pragma unroll
                for (int j = 0; j < 4; j++)
                    s[i][j] += q[i] * k[j];
        }

        // mask (key dim)
        {
            int kc = jt * 64 + 4 * tx;
#pragma unroll
            for (int j = 0; j < 4; j++) {
                if (mrow_g[kc + j] == 0) {
#pragma unroll
                    for (int i = 0; i < 4; i++) s[i][j] = -1e9f;
                }
            }
        }

        // online softmax: stats per row, replicated across the 16 tx lanes
#pragma unroll
        for (int i = 0; i < 4; i++) {
            float mx = fmaxf(fmaxf(s[i][0], s[i][1]), fmaxf(s[i][2], s[i][3]));
            mx = fmaxf(mx, __shfl_xor_sync(0xffffffffu, mx, 1));
            mx = fmaxf(mx, __shfl_xor_sync(0xffffffffu, mx, 2));
            mx = fmaxf(mx, __shfl_xor_sync(0xffffffffu, mx, 4));
            mx = fmaxf(mx, __shfl_xor_sync(0xffffffffu, mx, 8));
            float mnew = fmaxf(mr[i], mx);
            float alpha = __expf(mr[i] - mnew);
            float sum = 0.f;
#pragma unroll
            for (int j = 0; j < 4; j++) {
                s[i][j] = __expf(s[i][j] - mnew);
                sum += s[i][j];
            }
            sum += __shfl_xor_sync(0xffffffffu, sum, 1);
            sum += __shfl_xor_sync(0xffffffffu, sum, 2);
            sum += __shfl_xor_sync(0xffffffffu, sum, 4);
            sum += __shfl_xor_sync(0xffffffffu, sum, 8);
            lr_[i] = lr_[i] * alpha + sum;
            mr[i] = mnew;
#pragma unroll
            for (int j = 0; j < 4; j++) O[i][j] *= alpha;
            // store P transposed: Pt[c][r], stride 68
#pragma unroll
            for (int j = 0; j < 4; j++)
                Pt[(4 * tx + j) * 68 + 4 * ty + i] = s[i][j];
        }
        __syncthreads();

        // O += P @ V
#pragma unroll 8
        for (int k = 0; k < 64; k++) {
            float p[4], v[4];
            *(float4*)p = *(float4*)&Pt[k * 68 + 4 * ty];
            *(float4*)v = *(float4*)&Vs[k * 64 + 4 * tx];
#pragma unroll
            for (int i = 0; i < 4; i++)
#pragma unroll
                for (int j = 0; j < 4; j++)
                    O[i][j] += p[i] * v[j];
        }
    }

    // write att in [B, T, H, Dh]
#pragma unroll
    for (int i = 0; i < 4; i++) {
        float inv = 1.0f / lr_[i];
        int t = q0 + 4 * ty + i;
        size_t base = (((size_t)b * TT + t) * NH + head) * DH + 4 * tx;
        float4 o;
        o.x = O[i][0] * inv; o.y = O[i][1] * inv;
        o.z = O[i][2] * inv; o.w = O[i][3] * inv;
        *(float4*)&att[base] = o;
    }
}

// ---------------------------------------------------------------------------
// GEMM2: out = att @ w_out^T + b_out, plain row-major output.
// ---------------------------------------------------------------------------
__global__ __launch_bounds__(256) void out_kernel(const float* __restrict__ a_in,
                                                  const float* __restrict__ w,
                                                  const float* __restrict__ bias,
                                                  float* __restrict__ out) {
    __shared__ float As[16][64];
    __shared__ float Ws[16][64];
    const int tid = threadIdx.x;
    const int tx = tid & 15, ty = tid >> 4;
    const int n0 = blockIdx.x * 64, m0 = blockIdx.y * 64;
    const int lr = tid >> 2, lk = (tid & 3) * 4;

    const float* aptr = a_in + (size_t)(m0 + lr) * DM + lk;
    const float* wptr = w + (size_t)(n0 + lr) * DM + lk;

    float acc[4][4] = {};
    for (int k0 = 0; k0 < DM; k0 += 16) {
        float4 a4 = *(const float4*)(aptr + k0);
        float4 w4 = *(const float4*)(wptr + k0);
        As[lk + 0][lr] = a4.x; As[lk + 1][lr] = a4.y;
        As[lk + 2][lr] = a4.z; As[lk + 3][lr] = a4.w;
        Ws[lk + 0][lr] = w4.x; Ws[lk + 1][lr] = w4.y;
        Ws[lk + 2][lr] = w4.z; Ws[lk + 3][lr] = w4.w;
        __syncthreads();
#pragma unroll
        for (int k = 0; k < 16; k++) {
            float a[4], b[4];
            *(float4*)a = *(float4*)&As[k][4 * ty];
            *(float4*)b = *(float4*)&Ws[k][4 * tx];
#pragma unroll
            for (int i = 0; i < 4; i++)
#pragma unroll
                for (int j = 0; j < 4; j++)
                    acc[i][j] += a[i] * b[j];
        }
        __syncthreads();
    }

    float bia[4];
#pragma unroll
    for (int j = 0; j < 4; j++) bia[j] = bias[n0 + 4 * tx + j];

#pragma unroll
    for (int i = 0; i < 4; i++) {
        int m = m0 + 4 * ty + i;
        float4 o;
        o.x = acc[i][0] + bia[0];
        o.y = acc[i][1] + bia[1];
        o.z = acc[i][2] + bia[2];
        o.w = acc[i][3] + bia[3];
        *(float4*)&out[(size_t)m * DM + n0 + 4 * tx] = o;
    }
}

// ---------------------------------------------------------------------------
// Inputs (metadata order): x, w_qkv, b_qkv, w_out, b_out, mask. Output: float32.
// ---------------------------------------------------------------------------
extern "C" void kernel_launch(void* const* d_in, const int* in_sizes, int n_in,
                              void* d_out, int out_size) {
    const float* x     = (const float*)d_in[0];
    const float* w_qkv = (const float*)d_in[1];
    const float* b_qkv = (const float*)d_in[2];
    const float* w_out = (const float*)d_in[3];
    const float* b_out = (const float*)d_in[4];
    const int*   mask  = (const int*)d_in[5];
    float* out = (float*)d_out;

    static const size_t ATTN_SMEM = (3 * 64 * 64 + 64 * 68) * sizeof(float); // 66560
    cudaFuncSetAttribute(attn_kernel, cudaFuncAttributeMaxDynamicSharedMemorySize,
                         (int)ATTN_SMEM);

    float* att;
    cudaGetSymbolAddress((void**)&att, g_att);

    qkv_kernel<<<dim3(3 * DM / 64, BB * TT / 64), 256>>>(x, w_qkv, b_qkv);
    attn_kernel<<<dim3(TT / 64, BH), 256, ATTN_SMEM>>>(mask, att);
    out_kernel<<<dim3(DM / 64, BB * TT / 64), 256>>>(att, w_out, b_out, out);
}